// round 7
// baseline (speedup 1.0000x reference)
#include <cuda_runtime.h>
#include <cstdint>

// QualityAwarePatchAugment — GB300 sm_103a — R6.
// Persistent blocks, software-pipelined patches, double-buffered cp.async.
//   grid = 444 (= 148 SMs x 3 blocks), 256 threads; each block processes
//   patches bx, bx+444, ... (9-10 patches). While patch i is reduced and
//   applied, patch i+2's img tile is already streaming into the freed smem
//   buffer -> DRAM pipe never drains at phase seams (R3/R5's 4.2 TB/s vs
//   R1-apply's 5.1 TB/s gap).

#define STRIDE   444
#define NPATCH   4096

__device__ __forceinline__ float clipf(float v) {
    return fminf(fmaxf(v, 0.0f), 1.0f);
}

__device__ __forceinline__ void cp16(uint32_t smem_dst, const void* gptr) {
    asm volatile("cp.async.cg.shared.global [%0], [%1], 16;"
                 :: "r"(smem_dst), "l"(gptr));
}

// Issue this thread's 8 float4 copies of patch (ph,pw), batch b, into buf.
__device__ __forceinline__ void issue_patch(
    const float4* __restrict__ img, int p, int b, int l8, uint32_t buf_u)
{
    const int ph = p >> 6, pw = p & 63;
    const int f4base = (b << 18) + (ph << 12) + (pw << 2);
    const uint32_t dstb = buf_u + (b << 10);          // batch slice, 1 KB
    #pragma unroll
    for (int k = 0; k < 8; k++) {
        const int fi  = l8 + (k << 3);                // float4 slot 0..63
        const int row = fi >> 2;
        const int c4  = fi & 3;
        cp16(dstb + (((row << 4) + (c4 << 2)) << 2),
             img + f4base + (row << 8) + c4);
    }
    asm volatile("cp.async.commit_group;");
}

__global__ void __launch_bounds__(256, 3) fused_kernel(
    const float4* __restrict__ img,
    const float4* __restrict__ noise,
    float4*       __restrict__ out,
    const float*  __restrict__ r_strong,
    const float*  __restrict__ r_drop,
    const float*  __restrict__ r_else,
    const float*  __restrict__ bright_f,
    const float*  __restrict__ contrast_f,
    const float*  __restrict__ slight_f,
    const int*    __restrict__ aug_choice,
    const int*    __restrict__ slight_choice)
{
    extern __shared__ float dsm[];
    float* const buf[2] = { dsm, dsm + 8192 };        // 2 x 32 KB patch tiles
    float* const sh_s   = dsm + 16384;                // [32]
    float* const sh_s2  = sh_s + 32;                  // [32]
    float* const s_scal = sh_s2 + 32;                 // [8]

    const int bx   = blockIdx.x;
    const int t    = threadIdx.x;
    const int b    = t >> 3;                          // batch 0..31
    const int l8   = t & 7;
    const int lane = t & 31;

    const uint32_t buf_u[2] = {
        (uint32_t)__cvta_generic_to_shared(buf[0]),
        (uint32_t)__cvta_generic_to_shared(buf[1]) };

    // Prime the pipeline: patches bx and bx+STRIDE.
    issue_patch(img, bx, b, l8, buf_u[0]);
    if (bx + STRIDE < NPATCH) issue_patch(img, bx + STRIDE, b, l8, buf_u[1]);

    int i = 0;
    for (int p = bx; p < NPATCH; p += STRIDE, i++) {
        const int cur = i & 1;
        float* const sm_b = buf[cur] + (b << 8);

        // Per-patch decision scalars (mostly L2-resident after first wave).
        float myscal = 0.0f;
        if (t < 8) {
            switch (t) {
                case 0: myscal = r_strong[p];                      break;
                case 1: myscal = r_drop[p];                        break;
                case 2: myscal = r_else[p];                        break;
                case 3: myscal = bright_f[p];                      break;
                case 4: myscal = contrast_f[p];                    break;
                case 5: myscal = slight_f[p];                      break;
                case 6: myscal = __int_as_float(aug_choice[p]);    break;
                case 7: myscal = __int_as_float(slight_choice[p]); break;
            }
        }

        // Wait for this patch's tile (leave next patch's group in flight).
        if (p + STRIDE < NPATCH) {
            asm volatile("cp.async.wait_group 1;" ::: "memory");
        } else {
            asm volatile("cp.async.wait_group 0;" ::: "memory");
        }

        // ---- stats from own slots ----
        float s = 0.0f, s2 = 0.0f;
        #pragma unroll
        for (int k = 0; k < 8; k++) {
            const int fi = l8 + (k << 3);
            const float4 v = *reinterpret_cast<const float4*>(
                sm_b + ((fi >> 2) << 4) + ((fi & 3) << 2));
            s  += v.x + v.y + v.z + v.w;
            s2 += v.x * v.x + v.y * v.y + v.z * v.z + v.w * v.w;
        }
        #pragma unroll
        for (int off = 4; off; off >>= 1) {
            s  += __shfl_down_sync(0xffffffffu, s,  off, 8);
            s2 += __shfl_down_sync(0xffffffffu, s2, off, 8);
        }
        if (l8 == 0) { sh_s[b] = s; sh_s2[b] = s2; }
        if (t < 8)   { s_scal[t] = myscal; }
        __syncthreads();                               // bar1

        // ---- redundant per-warp batch fold (all lanes get q, mpp) ----
        float q, mpp;
        {
            const float bs  = sh_s[lane];
            const float bs2 = sh_s2[lane];
            const float mean = bs * (1.0f / 256.0f);
            float var = (bs2 - bs * bs * (1.0f / 256.0f)) * (1.0f / 255.0f);
            var = fmaxf(var, 0.0f);
            const float sd = sqrtf(var);
            const float iq = 1.0f - 2.0f * fabsf(mean - 0.5f);
            float qs  = (sd + iq + var) * (1.0f / 3.0f);
            float tot = bs;
            #pragma unroll
            for (int off = 16; off; off >>= 1) {
                qs  += __shfl_xor_sync(0xffffffffu, qs,  off);
                tot += __shfl_xor_sync(0xffffffffu, tot, off);
            }
            q   = qs  * (1.0f / 32.0f);
            mpp = tot * (1.0f / 8192.0f);
        }

        const bool low    = q < 0.7f;
        const bool strong = low && (s_scal[0] < 0.8f);
        const bool drop   = low && (q < 0.3f) && (s_scal[1] < 0.1f);
        const bool els    = (!low) && (s_scal[2] < 0.3f);

        int code = 0;
        if (strong) code = __float_as_int(s_scal[6]) + 1;
        if (els)    code = __float_as_int(s_scal[7]) + 5;
        if (drop)   code = 7;

        float param = 0.0f;
        switch (code) {
            case 1: param = 0.1f;       break;
            case 3: param = s_scal[3];  break;
            case 4: param = s_scal[4];  break;
            case 5: param = 0.05f;      break;
            case 6: param = s_scal[5];  break;
            default: break;
        }

        // ---- apply ----
        const int ph = p >> 6, pw = p & 63;
        const int f4base = (b << 18) + (ph << 12) + (pw << 2);

        if (code == 0) {                              // identity
            #pragma unroll
            for (int k = 0; k < 8; k++) {
                const int fi  = l8 + (k << 3);
                const int row = fi >> 2, c4 = fi & 3;
                const float4 v = *reinterpret_cast<const float4*>(
                    sm_b + (row << 4) + (c4 << 2));
                out[f4base + (row << 8) + c4] = v;
            }
        } else if (code == 1 || code == 5) {          // noise variants
            #pragma unroll
            for (int k = 0; k < 8; k++) {
                const int fi  = l8 + (k << 3);
                const int row = fi >> 2, c4 = fi & 3;
                const int gi  = f4base + (row << 8) + c4;
                const float4 v = *reinterpret_cast<const float4*>(
                    sm_b + (row << 4) + (c4 << 2));
                const float4 n = __ldcs(&noise[gi]);
                float4 o;
                o.x = clipf(fmaf(param, n.x, v.x));
                o.y = clipf(fmaf(param, n.y, v.y));
                o.z = clipf(fmaf(param, n.z, v.z));
                o.w = clipf(fmaf(param, n.w, v.w));
                out[gi] = o;
            }
        } else if (code == 2) {                       // 3x3 blur, zero-padded
            const float inv9 = 1.0f / 9.0f;
            #pragma unroll
            for (int k = 0; k < 8; k++) {
                const int fi  = l8 + (k << 3);
                const int row = fi >> 2;
                const int c0  = (fi & 3) << 2;
                float a0 = 0.f, a1 = 0.f, a2 = 0.f, a3 = 0.f;
                #pragma unroll
                for (int dr = -1; dr <= 1; dr++) {
                    const int r = row + dr;
                    if (r < 0 || r > 15) continue;
                    const float* rp = sm_b + (r << 4);
                    const float lft = (c0 > 0)  ? rp[c0 - 1] : 0.0f;
                    const float rgt = (c0 < 12) ? rp[c0 + 4] : 0.0f;
                    const float m0 = rp[c0], m1 = rp[c0 + 1];
                    const float m2 = rp[c0 + 2], m3 = rp[c0 + 3];
                    a0 += lft + m0 + m1;
                    a1 += m0 + m1 + m2;
                    a2 += m1 + m2 + m3;
                    a3 += m2 + m3 + rgt;
                }
                out[f4base + (row << 8) + (fi & 3)] =
                    make_float4(a0 * inv9, a1 * inv9, a2 * inv9, a3 * inv9);
            }
        } else if (code == 3 || code == 6) {          // brightness variants
            #pragma unroll
            for (int k = 0; k < 8; k++) {
                const int fi  = l8 + (k << 3);
                const int row = fi >> 2, c4 = fi & 3;
                const float4 v = *reinterpret_cast<const float4*>(
                    sm_b + (row << 4) + (c4 << 2));
                float4 o;
                o.x = clipf(v.x * param);
                o.y = clipf(v.y * param);
                o.z = clipf(v.z * param);
                o.w = clipf(v.w * param);
                out[f4base + (row << 8) + c4] = o;
            }
        } else if (code == 4) {                       // contrast about m_pp
            #pragma unroll
            for (int k = 0; k < 8; k++) {
                const int fi  = l8 + (k << 3);
                const int row = fi >> 2, c4 = fi & 3;
                const float4 v = *reinterpret_cast<const float4*>(
                    sm_b + (row << 4) + (c4 << 2));
                float4 o;
                o.x = clipf(fmaf(v.x - mpp, param, mpp));
                o.y = clipf(fmaf(v.y - mpp, param, mpp));
                o.z = clipf(fmaf(v.z - mpp, param, mpp));
                o.w = clipf(fmaf(v.w - mpp, param, mpp));
                out[f4base + (row << 8) + c4] = o;
            }
        } else {                                      // 7: drop
            const float4 z = make_float4(0.f, 0.f, 0.f, 0.f);
            #pragma unroll
            for (int k = 0; k < 8; k++) {
                const int fi = l8 + (k << 3);
                out[f4base + ((fi >> 2) << 8) + (fi & 3)] = z;
            }
        }

        __syncthreads();                               // bar2: buffer free

        // Prefetch patch i+2 into the buffer just released.
        if (p + 2 * STRIDE < NPATCH)
            issue_patch(img, p + 2 * STRIDE, b, l8, buf_u[cur]);
    }
}

extern "C" void kernel_launch(void* const* d_in, const int* in_sizes, int n_in,
                              void* d_out, int out_size)
{
    static const int SMEM_BYTES = (2 * 8192 + 32 + 32 + 8) * 4;   // ~65.8 KB
    cudaFuncSetAttribute(fused_kernel,
                         cudaFuncAttributeMaxDynamicSharedMemorySize,
                         SMEM_BYTES);
    fused_kernel<<<STRIDE, 256, SMEM_BYTES>>>(
        (const float4*)d_in[0],   // img
        (const float4*)d_in[1],   // noise
        (float4*)d_out,
        (const float*)d_in[2],    // r_strong
        (const float*)d_in[3],    // r_drop
        (const float*)d_in[4],    // r_else
        (const float*)d_in[5],    // bright_f
        (const float*)d_in[6],    // contrast_f
        (const float*)d_in[7],    // slight_f
        (const int*)d_in[8],      // aug_choice
        (const int*)d_in[9]);     // slight_choice
}

// round 8
// speedup vs baseline: 1.1567x; 1.1567x over previous
#include <cuda_runtime.h>

// QualityAwarePatchAugment — GB300 sm_103a — R7.
// One patch per 256-thread block, grid 4096. NO smem patch tile: phase 1
// streams img once from DRAM for stats; phase 3 re-reads the same lines as
// guaranteed L2 hits (within-block reuse distance ~10 MB << 126 MB L2).
// Single __syncthreads + redundant per-warp fold. smem ~300 B, so occupancy
// is reg-limited only (~5 blocks/SM) and there is zero STS/LDS traffic.

__device__ __forceinline__ float clipf(float v) {
    return fminf(fmaxf(v, 0.0f), 1.0f);
}

__global__ void __launch_bounds__(256) fused_kernel(
    const float4* __restrict__ img,
    const float4* __restrict__ noise,
    float4*       __restrict__ out,
    const float*  __restrict__ r_strong,
    const float*  __restrict__ r_drop,
    const float*  __restrict__ r_else,
    const float*  __restrict__ bright_f,
    const float*  __restrict__ contrast_f,
    const float*  __restrict__ slight_f,
    const int*    __restrict__ aug_choice,
    const int*    __restrict__ slight_choice)
{
    __shared__ float sh_s[32], sh_s2[32];
    __shared__ float s_scal[8];

    const int p    = blockIdx.x;            // patch index = ph*64 + pw
    const int ph   = p >> 6;
    const int pw   = p & 63;
    const int t    = threadIdx.x;
    const int b    = t >> 3;                // batch 0..31
    const int l8   = t & 7;                 // 8 threads per batch
    const int lane = t & 31;

    // Prefetch decision scalars before the barrier.
    if (t < 8) {
        float v;
        switch (t) {
            case 0: v = r_strong[p];                      break;
            case 1: v = r_drop[p];                        break;
            case 2: v = r_else[p];                        break;
            case 3: v = bright_f[p];                      break;
            case 4: v = contrast_f[p];                    break;
            case 5: v = slight_f[p];                      break;
            case 6: v = __int_as_float(aug_choice[p]);    break;
            default: v = __int_as_float(slight_choice[p]); break;
        }
        s_scal[t] = v;
    }

    // float4 base of (batch b, patch row 0); img row stride = 256 float4.
    const int f4base = (b << 18) + (ph << 12) + (pw << 2);

    // ---- Phase 1: stream patch from DRAM, stats only (values discarded) ---
    float s = 0.0f, s2 = 0.0f;
    #pragma unroll
    for (int k = 0; k < 8; k++) {
        const int fi  = l8 + (k << 3);      // float4 slot 0..63
        const float4 v = img[f4base + ((fi >> 2) << 8) + (fi & 3)];
        s  += v.x + v.y + v.z + v.w;
        s2 += v.x * v.x + v.y * v.y + v.z * v.z + v.w * v.w;
    }
    #pragma unroll
    for (int off = 4; off; off >>= 1) {
        s  += __shfl_down_sync(0xffffffffu, s,  off, 8);
        s2 += __shfl_down_sync(0xffffffffu, s2, off, 8);
    }
    if (l8 == 0) { sh_s[b] = s; sh_s2[b] = s2; }
    __syncthreads();                        // the only block-wide barrier

    // ---- Phase 2: redundant per-warp fold (all lanes get q, mpp) ----------
    float q, mpp;
    {
        const float bs  = sh_s[lane];
        const float bs2 = sh_s2[lane];
        const float mean = bs * (1.0f / 256.0f);
        float var = (bs2 - bs * bs * (1.0f / 256.0f)) * (1.0f / 255.0f); // ddof=1
        var = fmaxf(var, 0.0f);
        const float sd = sqrtf(var);
        const float iq = 1.0f - 2.0f * fabsf(mean - 0.5f);
        float qs  = (sd + iq + var) * (1.0f / 3.0f);
        float tot = bs;
        #pragma unroll
        for (int off = 16; off; off >>= 1) {
            qs  += __shfl_xor_sync(0xffffffffu, qs,  off);
            tot += __shfl_xor_sync(0xffffffffu, tot, off);
        }
        q   = qs  * (1.0f / 32.0f);
        mpp = tot * (1.0f / 8192.0f);       // 32 batches * 256 px
    }

    const bool low    = q < 0.7f;
    const bool strong = low && (s_scal[0] < 0.8f);
    const bool drop   = low && (q < 0.3f) && (s_scal[1] < 0.1f);
    const bool els    = (!low) && (s_scal[2] < 0.3f);

    int code = 0;
    if (strong) code = __float_as_int(s_scal[6]) + 1;   // aug_choice + 1
    if (els)    code = __float_as_int(s_scal[7]) + 5;   // slight_choice + 5
    if (drop)   code = 7;

    float param = 0.0f;
    switch (code) {
        case 1: param = 0.1f;       break;
        case 3: param = s_scal[3];  break;   // bright_f
        case 4: param = s_scal[4];  break;   // contrast_f
        case 5: param = 0.05f;      break;
        case 6: param = s_scal[5];  break;   // slight_f
        default: break;
    }

    // ---- Phase 3: apply; img re-read is an L2 hit (just loaded above) -----
    if (code == 0) {                              // identity (~20%)
        #pragma unroll
        for (int k = 0; k < 8; k++) {
            const int fi = l8 + (k << 3);
            const int gi = f4base + ((fi >> 2) << 8) + (fi & 3);
            out[gi] = img[gi];
        }
    } else if (code == 1 || code == 5) {          // noise / slight noise
        #pragma unroll
        for (int k = 0; k < 8; k++) {
            const int fi = l8 + (k << 3);
            const int gi = f4base + ((fi >> 2) << 8) + (fi & 3);
            const float4 v = img[gi];             // L2 hit
            const float4 n = __ldcs(&noise[gi]);  // DRAM, single-use
            float4 o;
            o.x = clipf(fmaf(param, n.x, v.x));
            o.y = clipf(fmaf(param, n.y, v.y));
            o.z = clipf(fmaf(param, n.z, v.z));
            o.w = clipf(fmaf(param, n.w, v.w));
            out[gi] = o;
        }
    } else if (code == 2) {                       // 3x3 blur, zero-pad in patch
        const float inv9 = 1.0f / 9.0f;
        const float* imgf = (const float*)img;
        #pragma unroll
        for (int k = 0; k < 8; k++) {
            const int fi  = l8 + (k << 3);
            const int row = fi >> 2;
            const int c4  = fi & 3;
            float a0 = 0.f, a1 = 0.f, a2 = 0.f, a3 = 0.f;
            #pragma unroll
            for (int dr = -1; dr <= 1; dr++) {
                const int r = row + dr;
                if (r < 0 || r > 15) continue;    // zero padding
                const int basef4 = f4base + (r << 8) + c4;  // float4 idx
                const int basepx = basef4 << 2;             // float idx
                const float4 vv = img[basef4];              // L2/L1 hit
                const float lft = (c4 > 0) ? __ldg(imgf + basepx - 1) : 0.0f;
                const float rgt = (c4 < 3) ? __ldg(imgf + basepx + 4) : 0.0f;
                a0 += lft  + vv.x + vv.y;
                a1 += vv.x + vv.y + vv.z;
                a2 += vv.y + vv.z + vv.w;
                a3 += vv.z + vv.w + rgt;
            }
            out[f4base + (row << 8) + c4] =
                make_float4(a0 * inv9, a1 * inv9, a2 * inv9, a3 * inv9);
        }
    } else if (code == 3 || code == 6) {          // brightness variants
        #pragma unroll
        for (int k = 0; k < 8; k++) {
            const int fi = l8 + (k << 3);
            const int gi = f4base + ((fi >> 2) << 8) + (fi & 3);
            const float4 v = img[gi];
            float4 o;
            o.x = clipf(v.x * param);
            o.y = clipf(v.y * param);
            o.z = clipf(v.z * param);
            o.w = clipf(v.w * param);
            out[gi] = o;
        }
    } else if (code == 4) {                       // contrast about m_pp
        #pragma unroll
        for (int k = 0; k < 8; k++) {
            const int fi = l8 + (k << 3);
            const int gi = f4base + ((fi >> 2) << 8) + (fi & 3);
            const float4 v = img[gi];
            float4 o;
            o.x = clipf(fmaf(v.x - mpp, param, mpp));
            o.y = clipf(fmaf(v.y - mpp, param, mpp));
            o.z = clipf(fmaf(v.z - mpp, param, mpp));
            o.w = clipf(fmaf(v.w - mpp, param, mpp));
            out[gi] = o;
        }
    } else {                                      // 7: drop -> zeros, no re-read
        const float4 z = make_float4(0.f, 0.f, 0.f, 0.f);
        #pragma unroll
        for (int k = 0; k < 8; k++) {
            const int fi = l8 + (k << 3);
            out[f4base + ((fi >> 2) << 8) + (fi & 3)] = z;
        }
    }
}

extern "C" void kernel_launch(void* const* d_in, const int* in_sizes, int n_in,
                              void* d_out, int out_size)
{
    fused_kernel<<<4096, 256>>>(
        (const float4*)d_in[0],   // img
        (const float4*)d_in[1],   // noise
        (float4*)d_out,
        (const float*)d_in[2],    // r_strong
        (const float*)d_in[3],    // r_drop
        (const float*)d_in[4],    // r_else
        (const float*)d_in[5],    // bright_f
        (const float*)d_in[6],    // contrast_f
        (const float*)d_in[7],    // slight_f
        (const int*)d_in[8],      // aug_choice
        (const int*)d_in[9]);     // slight_choice
}

// round 11
// speedup vs baseline: 1.3029x; 1.1264x over previous
#include <cuda_runtime.h>

// QualityAwarePatchAugment — GB300 sm_103a — R8.
// R3 skeleton (register patch cache = landing regs, MLP 8) with:
//   - ONE __syncthreads + redundant per-warp butterfly fold (from R5)
//   - smem tile STS + its barrier only inside the blur branch (code is
//     block-uniform, so the conditional barrier is legal); ~80% of blocks
//     touch no smem data at all.

__device__ __forceinline__ float clipf(float v) {
    return fminf(fmaxf(v, 0.0f), 1.0f);
}

__global__ void __launch_bounds__(256) fused_kernel(
    const float4* __restrict__ img,
    const float4* __restrict__ noise,
    float4*       __restrict__ out,
    const float*  __restrict__ r_strong,
    const float*  __restrict__ r_drop,
    const float*  __restrict__ r_else,
    const float*  __restrict__ bright_f,
    const float*  __restrict__ contrast_f,
    const float*  __restrict__ slight_f,
    const int*    __restrict__ aug_choice,
    const int*    __restrict__ slight_choice)
{
    __shared__ float sm[32 * 256];          // patch tile; used ONLY for blur
    __shared__ float sh_s[32], sh_s2[32];
    __shared__ float s_scal[8];

    const int p    = blockIdx.x;            // patch index = ph*64 + pw
    const int ph   = p >> 6;
    const int pw   = p & 63;
    const int t    = threadIdx.x;
    const int b    = t >> 3;                // batch 0..31
    const int l8   = t & 7;                 // 8 threads per batch
    const int lane = t & 31;

    // Prefetch decision scalars (before the barrier).
    if (t < 8) {
        float v;
        switch (t) {
            case 0: v = r_strong[p];                       break;
            case 1: v = r_drop[p];                         break;
            case 2: v = r_else[p];                         break;
            case 3: v = bright_f[p];                       break;
            case 4: v = contrast_f[p];                     break;
            case 5: v = slight_f[p];                       break;
            case 6: v = __int_as_float(aug_choice[p]);     break;
            default: v = __int_as_float(slight_choice[p]); break;
        }
        s_scal[t] = v;
    }

    // float4 base of (batch b, patch row 0); img row stride = 256 float4.
    const int f4base = (b << 18) + (ph << 12) + (pw << 2);

    // ---- Phase 1: load 8 float4s into registers (cache == landing regs) ---
    float4 v[8];
    float s = 0.0f, s2 = 0.0f;
    #pragma unroll
    for (int k = 0; k < 8; k++) {
        const int fi = l8 + (k << 3);       // slot 0..63; row=fi>>2, c4=fi&3
        v[k] = img[f4base + ((fi >> 2) << 8) + (fi & 3)];
        s  += v[k].x + v[k].y + v[k].z + v[k].w;
        s2 += v[k].x * v[k].x + v[k].y * v[k].y
            + v[k].z * v[k].z + v[k].w * v[k].w;
    }
    #pragma unroll
    for (int off = 4; off; off >>= 1) {
        s  += __shfl_down_sync(0xffffffffu, s,  off, 8);
        s2 += __shfl_down_sync(0xffffffffu, s2, off, 8);
    }
    if (l8 == 0) { sh_s[b] = s; sh_s2[b] = s2; }
    __syncthreads();                        // the only unconditional barrier

    // ---- Phase 2: redundant per-warp butterfly fold (all lanes get q,mpp) -
    float q, mpp;
    {
        const float bs  = sh_s[lane];
        const float bs2 = sh_s2[lane];
        const float mean = bs * (1.0f / 256.0f);
        float var = (bs2 - bs * bs * (1.0f / 256.0f)) * (1.0f / 255.0f); // ddof=1
        var = fmaxf(var, 0.0f);
        const float sd = sqrtf(var);
        const float iq = 1.0f - 2.0f * fabsf(mean - 0.5f);
        float qs  = (sd + iq + var) * (1.0f / 3.0f);
        float tot = bs;
        #pragma unroll
        for (int off = 16; off; off >>= 1) {
            qs  += __shfl_xor_sync(0xffffffffu, qs,  off);
            tot += __shfl_xor_sync(0xffffffffu, tot, off);
        }
        q   = qs  * (1.0f / 32.0f);
        mpp = tot * (1.0f / 8192.0f);       // 32 batches * 256 px
    }

    const bool low    = q < 0.7f;
    const bool strong = low && (s_scal[0] < 0.8f);
    const bool drop   = low && (q < 0.3f) && (s_scal[1] < 0.1f);
    const bool els    = (!low) && (s_scal[2] < 0.3f);

    int code = 0;
    if (strong) code = __float_as_int(s_scal[6]) + 1;   // aug_choice + 1
    if (els)    code = __float_as_int(s_scal[7]) + 5;   // slight_choice + 5
    if (drop)   code = 7;

    float param = 0.0f;
    switch (code) {
        case 1: param = 0.1f;       break;
        case 3: param = s_scal[3];  break;   // bright_f
        case 4: param = s_scal[4];  break;   // contrast_f
        case 5: param = 0.05f;      break;
        case 6: param = s_scal[5];  break;   // slight_f
        default: break;
    }

    // ---- Phase 3: apply (block-uniform branch; data lives in registers) ---
    if (code == 0) {                              // identity (~20%)
        #pragma unroll
        for (int k = 0; k < 8; k++) {
            const int fi = l8 + (k << 3);
            out[f4base + ((fi >> 2) << 8) + (fi & 3)] = v[k];
        }
    } else if (code == 1 || code == 5) {          // noise / slight noise
        #pragma unroll
        for (int k = 0; k < 8; k++) {
            const int fi = l8 + (k << 3);
            const int gi = f4base + ((fi >> 2) << 8) + (fi & 3);
            const float4 n = __ldcs(&noise[gi]);
            float4 o;
            o.x = clipf(fmaf(param, n.x, v[k].x));
            o.y = clipf(fmaf(param, n.y, v[k].y));
            o.z = clipf(fmaf(param, n.z, v[k].z));
            o.w = clipf(fmaf(param, n.w, v[k].w));
            out[gi] = o;
        }
    } else if (code == 2) {                       // 3x3 blur: needs neighbors
        float* const sm_b = sm + (b << 8);        // [row16][col16] slice
        #pragma unroll
        for (int k = 0; k < 8; k++) {             // spill patch to smem
            const int fi = l8 + (k << 3);
            *reinterpret_cast<float4*>(
                sm_b + ((fi >> 2) << 4) + ((fi & 3) << 2)) = v[k];
        }
        __syncthreads();                          // uniform: all threads here
        const float inv9 = 1.0f / 9.0f;
        #pragma unroll
        for (int k = 0; k < 8; k++) {
            const int fi  = l8 + (k << 3);
            const int row = fi >> 2;
            const int c0  = (fi & 3) << 2;
            float a0 = 0.f, a1 = 0.f, a2 = 0.f, a3 = 0.f;
            #pragma unroll
            for (int dr = -1; dr <= 1; dr++) {
                const int r = row + dr;
                if (r < 0 || r > 15) continue;    // zero padding in patch
                const float* rp = sm_b + (r << 4);
                const float lft = (c0 > 0)  ? rp[c0 - 1] : 0.0f;
                const float rgt = (c0 < 12) ? rp[c0 + 4] : 0.0f;
                const float m0 = rp[c0], m1 = rp[c0 + 1];
                const float m2 = rp[c0 + 2], m3 = rp[c0 + 3];
                a0 += lft + m0 + m1;
                a1 += m0 + m1 + m2;
                a2 += m1 + m2 + m3;
                a3 += m2 + m3 + rgt;
            }
            out[f4base + (row << 8) + (fi & 3)] =
                make_float4(a0 * inv9, a1 * inv9, a2 * inv9, a3 * inv9);
        }
    } else if (code == 3 || code == 6) {          // brightness variants
        #pragma unroll
        for (int k = 0; k < 8; k++) {
            const int fi = l8 + (k << 3);
            float4 o;
            o.x = clipf(v[k].x * param);
            o.y = clipf(v[k].y * param);
            o.z = clipf(v[k].z * param);
            o.w = clipf(v[k].w * param);
            out[f4base + ((fi >> 2) << 8) + (fi & 3)] = o;
        }
    } else if (code == 4) {                       // contrast about m_pp
        #pragma unroll
        for (int k = 0; k < 8; k++) {
            const int fi = l8 + (k << 3);
            float4 o;
            o.x = clipf(fmaf(v[k].x - mpp, param, mpp));
            o.y = clipf(fmaf(v[k].y - mpp, param, mpp));
            o.z = clipf(fmaf(v[k].z - mpp, param, mpp));
            o.w = clipf(fmaf(v[k].w - mpp, param, mpp));
            out[f4base + ((fi >> 2) << 8) + (fi & 3)] = o;
        }
    } else {                                      // 7: drop -> zeros
        const float4 z = make_float4(0.f, 0.f, 0.f, 0.f);
        #pragma unroll
        for (int k = 0; k < 8; k++) {
            const int fi = l8 + (k << 3);
            out[f4base + ((fi >> 2) << 8) + (fi & 3)] = z;
        }
    }
}

extern "C" void kernel_launch(void* const* d_in, const int* in_sizes, int n_in,
                              void* d_out, int out_size)
{
    fused_kernel<<<4096, 256>>>(
        (const float4*)d_in[0],   // img
        (const float4*)d_in[1],   // noise
        (float4*)d_out,
        (const float*)d_in[2],    // r_strong
        (const float*)d_in[3],    // r_drop
        (const float*)d_in[4],    // r_else
        (const float*)d_in[5],    // bright_f
        (const float*)d_in[6],    // contrast_f
        (const float*)d_in[7],    // slight_f
        (const int*)d_in[8],      // aug_choice
        (const int*)d_in[9]);     // slight_choice
}